// round 3
// baseline (speedup 1.0000x reference)
#include <cuda_runtime.h>
#include <cstdint>

// VectorQuantizer: for each of N=65536 points (C=64), find nearest of K=512
// codebook rows (squared L2), output the selected row, NCHW layout.
//
// Strategy: whole codebook (128KB) + e_sq (2KB) in SMEM per CTA. One point per
// thread, x pre-packed into f32x2 register pairs, K-loop does broadcast
// LDS.128 + packed fma.rn.f32x2 (FFMA2). Score replicates the reference's
// fp32 rounding: (x_sq + e_sq[k]) - 2*cross, ties -> lowest k.

#define C_DIM     64
#define K_EMB     512
#define HW        1024        // 32*32
#define NPTS      65536       // 64*32*32
#define NTHREADS  512
#define NCTAS     148
#define PPC       443         // ceil(65536/148)
#define SMEM_BYTES (K_EMB * C_DIM * 4 + K_EMB * 4)

extern __shared__ float vq_smem[];

__device__ __forceinline__ void fma2(unsigned long long& d,
                                     unsigned long long a,
                                     unsigned long long b) {
    asm("fma.rn.f32x2 %0, %1, %2, %0;" : "+l"(d) : "l"(a), "l"(b));
}
__device__ __forceinline__ unsigned long long pack2(float lo, float hi) {
    unsigned long long r;
    asm("mov.b64 %0, {%1, %2};" : "=l"(r) : "f"(lo), "f"(hi));
    return r;
}
__device__ __forceinline__ void unpack2(float& lo, float& hi, unsigned long long v) {
    asm("mov.b64 {%0, %1}, %2;" : "=f"(lo), "=f"(hi) : "l"(v));
}

__global__ __launch_bounds__(NTHREADS, 1)
void vq_kernel(const float* __restrict__ x,
               const float* __restrict__ embed,
               float* __restrict__ out) {
    float* sE   = vq_smem;                 // K_EMB * C_DIM floats
    float* sEsq = vq_smem + K_EMB * C_DIM; // K_EMB floats

    const int tid = threadIdx.x;

    // ---- Stage codebook into SMEM (coalesced float4) ----
    {
        const float4* eg = reinterpret_cast<const float4*>(embed);
        float4* sg = reinterpret_cast<float4*>(sE);
        #pragma unroll
        for (int i = 0; i < (K_EMB * C_DIM / 4) / NTHREADS; i++)  // 16 iters
            sg[tid + i * NTHREADS] = eg[tid + i * NTHREADS];
    }
    __syncthreads();

    // ---- e_sq per codebook row (sequential fp32 order, like the reference) ----
    {
        const float* row = sE + tid * C_DIM;   // tid in [0,512) == K_EMB
        float s = 0.0f;
        #pragma unroll
        for (int c = 0; c < C_DIM; c++) s = fmaf(row[c], row[c], s);
        sEsq[tid] = s;
    }
    __syncthreads();

    // ---- One point per thread ----
    const int n = blockIdx.x * PPC + tid;
    const bool valid = (tid < PPC) && (n < NPTS);

    int bestk = 0;
    if (valid) {
        const int b  = n >> 10;      // n / 1024
        const int hw = n & 1023;
        const float* xp = x + (size_t)b * (C_DIM * HW) + hw;

        // Load x into registers, sequential x_sq, pack channel pairs for f32x2.
        unsigned long long xq[C_DIM / 2];
        float x_sq = 0.0f;
        #pragma unroll
        for (int c = 0; c < C_DIM / 2; c++) {
            float a0 = xp[(size_t)(2 * c)     * HW];
            float a1 = xp[(size_t)(2 * c + 1) * HW];
            x_sq = fmaf(a0, a0, x_sq);
            x_sq = fmaf(a1, a1, x_sq);
            xq[c] = pack2(a0, a1);
        }

        float best = 3.4e38f;
        const ulonglong2* sE2 = reinterpret_cast<const ulonglong2*>(sE);

        #pragma unroll 1
        for (int k = 0; k < K_EMB; k++) {
            const ulonglong2* row = sE2 + k * 16;   // 64 floats = 16 x 16B
            unsigned long long a0 = 0ULL, a1 = 0ULL;
            #pragma unroll
            for (int i = 0; i < 16; i += 2) {
                ulonglong2 e0 = row[i];       // LDS.128 broadcast (all lanes same k)
                ulonglong2 e1 = row[i + 1];
                fma2(a0, xq[2 * i],     e0.x);
                fma2(a1, xq[2 * i + 1], e0.y);
                fma2(a0, xq[2 * i + 2], e1.x);
                fma2(a1, xq[2 * i + 3], e1.y);
            }
            float l0, h0, l1, h1;
            unpack2(l0, h0, a0);
            unpack2(l1, h1, a1);
            float cross = (l0 + h0) + (l1 + h1);
            // Reference rounding: fl(fl(x_sq + e_sq) - fl(2*cross)).
            // 2*cross is exact in fp32 so the fused form matches bitwise.
            float t = x_sq + sEsq[k];
            float score = fmaf(-2.0f, cross, t);
            if (score < best) { best = score; bestk = k; }   // strict <: first-index ties
        }

        // ---- Gather selected row, strided NCHW store (coalesced across warp) ----
        const float* q = sE + bestk * C_DIM;
        float* op = out + (size_t)b * (C_DIM * HW) + hw;
        #pragma unroll
        for (int c = 0; c < C_DIM; c++)
            op[(size_t)c * HW] = q[c];
    }
}

extern "C" void kernel_launch(void* const* d_in, const int* in_sizes, int n_in,
                              void* d_out, int out_size) {
    const float* x     = (const float*)d_in[0];   // 64*64*32*32 fp32
    const float* embed = (const float*)d_in[1];   // 512*64 fp32
    float* out = (float*)d_out;                   // 64*64*32*32 fp32

    static bool attr_set = false;
    if (!attr_set) {
        cudaFuncSetAttribute(vq_kernel,
                             cudaFuncAttributeMaxDynamicSharedMemorySize,
                             SMEM_BYTES);
        attr_set = true;
    }
    vq_kernel<<<NCTAS, NTHREADS, SMEM_BYTES>>>(x, embed, out);
}

// round 7
// speedup vs baseline: 1.3353x; 1.3353x over previous
#include <cuda_runtime.h>
#include <cstdint>

// VectorQuantizer R3: 2 points per thread to halve broadcast-LDS traffic
// (R2 was L1/shared-bound at 82%). Per-point math is bit-identical to R2
// (which achieved rel_err = 0.0): same 4-lane stride-4 f32x2 accumulation,
// same (x_sq + e_sq) - 2*cross rounding, strict < (first-index ties).

#define C_DIM     64
#define K_EMB     512
#define HW        1024        // 32*32
#define NPTS      65536       // 64*32*32
#define NTHREADS  256
#define NCTAS     148
#define PPC       443         // ceil(65536/148), <= 2*NTHREADS
#define SMEM_BYTES (K_EMB * C_DIM * 4 + K_EMB * 4)

extern __shared__ float vq_smem[];

__device__ __forceinline__ void fma2(unsigned long long& d,
                                     unsigned long long a,
                                     unsigned long long b) {
    asm("fma.rn.f32x2 %0, %1, %2, %0;" : "+l"(d) : "l"(a), "l"(b));
}
__device__ __forceinline__ unsigned long long pack2(float lo, float hi) {
    unsigned long long r;
    asm("mov.b64 %0, {%1, %2};" : "=l"(r) : "f"(lo), "f"(hi));
    return r;
}
__device__ __forceinline__ void unpack2(float& lo, float& hi, unsigned long long v) {
    asm("mov.b64 {%0, %1}, %2;" : "=f"(lo), "=f"(hi) : "l"(v));
}

__global__ __launch_bounds__(NTHREADS, 1)
void vq_kernel(const float* __restrict__ x,
               const float* __restrict__ embed,
               float* __restrict__ out) {
    float* sE   = vq_smem;                 // K_EMB * C_DIM floats
    float* sEsq = vq_smem + K_EMB * C_DIM; // K_EMB floats

    const int tid = threadIdx.x;

    // ---- Stage codebook into SMEM (coalesced float4) ----
    {
        const float4* eg = reinterpret_cast<const float4*>(embed);
        float4* sg = reinterpret_cast<float4*>(sE);
        #pragma unroll
        for (int i = 0; i < (K_EMB * C_DIM / 4) / NTHREADS; i++)  // 32 iters
            sg[tid + i * NTHREADS] = eg[tid + i * NTHREADS];
    }
    __syncthreads();

    // ---- e_sq per codebook row (2 rows per thread), sequential fp32 order ----
    #pragma unroll
    for (int r = 0; r < 2; r++) {
        const int krow = tid + r * NTHREADS;
        const float* row = sE + krow * C_DIM;
        float s = 0.0f;
        #pragma unroll
        for (int c = 0; c < C_DIM; c++) s = fmaf(row[c], row[c], s);
        sEsq[krow] = s;
    }
    __syncthreads();

    // ---- Two points per thread ----
    const int base = blockIdx.x * PPC;
    const int n0 = base + tid;                       // always < NPTS (147*443+255)
    const bool v1 = (tid < PPC - NTHREADS) && (base + NTHREADS + tid < NPTS);
    const int n1 = v1 ? (base + NTHREADS + tid) : n0; // clamp: compute garbage, skip store

    const int b0 = n0 >> 10, hw0 = n0 & 1023;
    const int b1 = n1 >> 10, hw1 = n1 & 1023;
    const float* xp0 = x + (size_t)b0 * (C_DIM * HW) + hw0;
    const float* xp1 = x + (size_t)b1 * (C_DIM * HW) + hw1;

    unsigned long long xq0[C_DIM / 2], xq1[C_DIM / 2];
    float xsq0 = 0.0f, xsq1 = 0.0f;
    #pragma unroll
    for (int c = 0; c < C_DIM / 2; c++) {
        float a0 = xp0[(size_t)(2 * c)     * HW];
        float a1 = xp0[(size_t)(2 * c + 1) * HW];
        xsq0 = fmaf(a0, a0, xsq0);
        xsq0 = fmaf(a1, a1, xsq0);
        xq0[c] = pack2(a0, a1);
        float c0 = xp1[(size_t)(2 * c)     * HW];
        float c1 = xp1[(size_t)(2 * c + 1) * HW];
        xsq1 = fmaf(c0, c0, xsq1);
        xsq1 = fmaf(c1, c1, xsq1);
        xq1[c] = pack2(c0, c1);
    }

    float best0 = 3.4e38f, best1 = 3.4e38f;
    int bestk0 = 0, bestk1 = 0;
    const ulonglong2* sE2 = reinterpret_cast<const ulonglong2*>(sE);

    #pragma unroll 1
    for (int k = 0; k < K_EMB; k++) {
        const ulonglong2* row = sE2 + k * 16;   // 64 floats = 16 x 16B
        unsigned long long a0 = 0ULL, a1 = 0ULL;   // point 0 accumulators
        unsigned long long c0 = 0ULL, c1 = 0ULL;   // point 1 accumulators
        #pragma unroll
        for (int i = 0; i < 16; i += 2) {
            ulonglong2 e0 = row[i];       // broadcast LDS.128, shared by both points
            ulonglong2 e1 = row[i + 1];
            fma2(a0, xq0[2 * i],     e0.x);
            fma2(a1, xq0[2 * i + 1], e0.y);
            fma2(c0, xq1[2 * i],     e0.x);
            fma2(c1, xq1[2 * i + 1], e0.y);
            fma2(a0, xq0[2 * i + 2], e1.x);
            fma2(a1, xq0[2 * i + 3], e1.y);
            fma2(c0, xq1[2 * i + 2], e1.x);
            fma2(c1, xq1[2 * i + 3], e1.y);
        }
        const float esq = sEsq[k];
        {
            float l0, h0, l1, h1;
            unpack2(l0, h0, a0);
            unpack2(l1, h1, a1);
            float cross = (l0 + h0) + (l1 + h1);
            float t = xsq0 + esq;
            float score = fmaf(-2.0f, cross, t);
            if (score < best0) { best0 = score; bestk0 = k; }
        }
        {
            float l0, h0, l1, h1;
            unpack2(l0, h0, c0);
            unpack2(l1, h1, c1);
            float cross = (l0 + h0) + (l1 + h1);
            float t = xsq1 + esq;
            float score = fmaf(-2.0f, cross, t);
            if (score < best1) { best1 = score; bestk1 = k; }
        }
    }

    // ---- Gather selected rows, strided NCHW stores (coalesced across warp) ----
    {
        const float* q = sE + bestk0 * C_DIM;
        float* op = out + (size_t)b0 * (C_DIM * HW) + hw0;
        #pragma unroll
        for (int c = 0; c < C_DIM; c++)
            op[(size_t)c * HW] = q[c];
    }
    if (v1) {
        const float* q = sE + bestk1 * C_DIM;
        float* op = out + (size_t)b1 * (C_DIM * HW) + hw1;
        #pragma unroll
        for (int c = 0; c < C_DIM; c++)
            op[(size_t)c * HW] = q[c];
    }
}

extern "C" void kernel_launch(void* const* d_in, const int* in_sizes, int n_in,
                              void* d_out, int out_size) {
    const float* x     = (const float*)d_in[0];   // 64*64*32*32 fp32
    const float* embed = (const float*)d_in[1];   // 512*64 fp32
    float* out = (float*)d_out;                   // 64*64*32*32 fp32

    static bool attr_set = false;
    if (!attr_set) {
        cudaFuncSetAttribute(vq_kernel,
                             cudaFuncAttributeMaxDynamicSharedMemorySize,
                             SMEM_BYTES);
        attr_set = true;
    }
    vq_kernel<<<NCTAS, NTHREADS, SMEM_BYTES>>>(x, embed, out);
}